// round 8
// baseline (speedup 1.0000x reference)
#include <cuda_runtime.h>
#include <cstdint>

// Problem constants (fixed shape (8,2048,2048) fp32, ratio 0.1)
#define N_ELEMS   33554432
#define N_VEC4    (N_ELEMS / 4)
#define K_TOP     3355443           // int(0.1 * N)
#define SBINS     8192              // sample histogram bins (top 13 bits of 31-bit key)
#define SSHIFT    18
#define WIN_BINS  (1 << 20)         // window: 4 coarse sample bins = 2^20 key values
#define NBUCK     4096              // in-window buckets of 256 key values each
#define EQ_CAP    65536
#define LIST_CAP  (1 << 21)         // 2M staged i4 indices (expected ~830K)
#define STAGE_CAP 2048              // per-block staging (mean ~810)
#define SAMPLE_V4 262144            // 1/32 of float4s sampled
#define STARGET   (K_TOP / 32)

#define GRID_MAIN 1024              // 1024*256 = 262144 threads; N_VEC4 divisible
#define BLK_MAIN  256
#define GRID_FIX  256
#define BLK_FIX   256

__device__ unsigned int g_shist[SBINS];
__device__ unsigned int g_hA[NBUCK];
__device__ unsigned int g_above;
__device__ unsigned int g_lo;
__device__ unsigned int g_nList;
__device__ unsigned int g_i4List[LIST_CAP];
__device__ unsigned int g_eqCount;
__device__ uint2        g_eq[EQ_CAP];
__device__ unsigned int g_done;

// ---------------------------------------------------------------------------
// Zero per-replay scratch (small: ~50 KB).
__global__ void k_zero() {
    int tid = blockIdx.x * blockDim.x + threadIdx.x;
    int stride = gridDim.x * blockDim.x;
    for (int i = tid; i < SBINS; i += stride) g_shist[i] = 0;
    for (int i = tid; i < NBUCK; i += stride) g_hA[i] = 0;
    if (tid == 0) { g_above = 0; g_eqCount = 0; g_nList = 0; g_done = 0; }
}

// ---------------------------------------------------------------------------
// Sample 1/32 of the data into a 13-bit shared histogram, flush to global.
__global__ void k_sample(const float4* __restrict__ x) {
    __shared__ unsigned int sh[SBINS];
    for (int i = threadIdx.x; i < SBINS; i += blockDim.x) sh[i] = 0;
    __syncthreads();

    int tid = blockIdx.x * blockDim.x + threadIdx.x;
    int stride = gridDim.x * blockDim.x;
    for (int i = tid; i < SAMPLE_V4; i += stride) {
        int p = ((i >> 6) << 11) + (i & 63);   // 64 f4 per 2048-f4 group
        float4 v = x[p];
        atomicAdd(&sh[(__float_as_uint(v.x) & 0x7FFFFFFFu) >> SSHIFT], 1u);
        atomicAdd(&sh[(__float_as_uint(v.y) & 0x7FFFFFFFu) >> SSHIFT], 1u);
        atomicAdd(&sh[(__float_as_uint(v.z) & 0x7FFFFFFFu) >> SSHIFT], 1u);
        atomicAdd(&sh[(__float_as_uint(v.w) & 0x7FFFFFFFu) >> SSHIFT], 1u);
    }
    __syncthreads();
    for (int i = threadIdx.x; i < SBINS; i += blockDim.x) {
        unsigned int c = sh[i];
        if (c) atomicAdd(&g_shist[i], c);
    }
}

// ---------------------------------------------------------------------------
// Locate the coarse sample bin of the estimated k-th value; open the window.
__global__ void k_sscan() {
    __shared__ unsigned int suf[1024];
    int t = threadIdx.x;
    unsigned int s = 0;
#pragma unroll
    for (int j = 0; j < 8; j++) s += g_shist[t * 8 + j];
    suf[t] = s;
    __syncthreads();
    for (int d = 1; d < 1024; d <<= 1) {
        unsigned int v = (t + d < 1024) ? suf[t + d] : 0;
        __syncthreads();
        suf[t] += v;
        __syncthreads();
    }
    unsigned int segAbove = (t < 1023) ? suf[t + 1] : 0;
    if (suf[t] >= (unsigned)STARGET && segAbove < (unsigned)STARGET) {
        unsigned int acc = segAbove;
        int bin = t * 8;
        for (int j = 7; j >= 0; j--) {
            acc += g_shist[t * 8 + j];
            if (acc >= (unsigned)STARGET) { bin = t * 8 + j; break; }
        }
        int lo_bin = bin >= 2 ? bin - 2 : 0;
        if (lo_bin > SBINS - 4) lo_bin = SBINS - 4;
        g_lo = (unsigned)lo_bin << SSHIFT;
    }
}

// ---------------------------------------------------------------------------
// FUSED streaming pass (R6 body + bucket histogram): read x, write provisional
// out (keep iff b>=hi), count 'above', bucket-histogram window elements
// (rare smem atomics), stage i4 of any window-touching float4 (one ballot/f4).
__global__ void __launch_bounds__(BLK_MAIN) k_main(const float4* __restrict__ x,
                                                   float4* __restrict__ out) {
    __shared__ unsigned s_hist[NBUCK];
    __shared__ unsigned s_stage[STAGE_CAP];
    __shared__ unsigned s_count, s_above, s_base;

    for (int j = threadIdx.x; j < NBUCK; j += BLK_MAIN) s_hist[j] = 0;
    if (threadIdx.x == 0) { s_count = 0; s_above = 0; }
    __syncthreads();

    const unsigned lo = g_lo;
    const unsigned hi = lo + WIN_BINS;
    const unsigned lane = threadIdx.x & 31u;
    const unsigned stride = GRID_MAIN * BLK_MAIN;
    unsigned above = 0;

    // exactly 32 iterations per thread; warps always fully converged
    for (unsigned i = blockIdx.x * blockDim.x + threadIdx.x; i < (unsigned)N_VEC4;
         i += stride) {
        float4 v = x[i];
        unsigned b0 = __float_as_uint(v.x) & 0x7FFFFFFFu;
        unsigned b1 = __float_as_uint(v.y) & 0x7FFFFFFFu;
        unsigned b2 = __float_as_uint(v.z) & 0x7FFFFFFFu;
        unsigned b3 = __float_as_uint(v.w) & 0x7FFFFFFFu;
        float4 o;
        o.x = (b0 >= hi) ? v.x : 0.0f;
        o.y = (b1 >= hi) ? v.y : 0.0f;
        o.z = (b2 >= hi) ? v.z : 0.0f;
        o.w = (b3 >= hi) ? v.w : 0.0f;
        out[i] = o;
        above += (b0 >= hi) + (b1 >= hi) + (b2 >= hi) + (b3 >= hi);

        // unsigned wrap: b<lo -> huge -> false
        bool w0 = (b0 - lo) < WIN_BINS, w1 = (b1 - lo) < WIN_BINS;
        bool w2 = (b2 - lo) < WIN_BINS, w3 = (b3 - lo) < WIN_BINS;
        if (w0) atomicAdd(&s_hist[(b0 - lo) >> 8], 1u);
        if (w1) atomicAdd(&s_hist[(b1 - lo) >> 8], 1u);
        if (w2) atomicAdd(&s_hist[(b2 - lo) >> 8], 1u);
        if (w3) atomicAdd(&s_hist[(b3 - lo) >> 8], 1u);

        bool win = w0 | w1 | w2 | w3;
        unsigned m = __ballot_sync(0xFFFFFFFFu, win);
        if (m) {
            int leader = __ffs(m) - 1;
            unsigned base;
            if ((int)lane == leader)
                base = atomicAdd(&s_count, (unsigned)__popc(m));
            base = __shfl_sync(0xFFFFFFFFu, base, leader);
            if (win) {
                unsigned pos = base + __popc(m & ((1u << lane) - 1u));
                if (pos < STAGE_CAP) s_stage[pos] = i;
            }
        }
    }

#pragma unroll
    for (int off = 16; off; off >>= 1) above += __shfl_down_sync(0xFFFFFFFFu, above, off);
    if (lane == 0 && above) atomicAdd(&s_above, above);
    __syncthreads();

    if (threadIdx.x == 0) {
        if (s_above) atomicAdd(&g_above, s_above);
        unsigned n = s_count < STAGE_CAP ? s_count : STAGE_CAP;
        s_base = atomicAdd(&g_nList, n);
        s_count = n;
    }
    __syncthreads();

    for (int j = threadIdx.x; j < NBUCK; j += BLK_MAIN) {
        unsigned c = s_hist[j];
        if (c) atomicAdd(&g_hA[j], c);
    }
    unsigned n = s_count, base = s_base;
    for (unsigned j = threadIdx.x; j < n; j += BLK_MAIN) {
        unsigned pos = base + j;
        if (pos < LIST_CAP) g_i4List[pos] = s_stage[j];
    }
}

// ---------------------------------------------------------------------------
// Tail, single kernel. Every block redundantly scans the 4096-bucket histogram
// (same deterministic result), streams its slice of the i4 list (write sure
// keepers, collect winning-bucket elements), and the last block to finish does
// the exact selection by (|value| desc, index asc) — lax.top_k stable order.
__global__ void __launch_bounds__(BLK_FIX) k_fixsel(const float4* __restrict__ x,
                                                    float* __restrict__ out) {
    __shared__ unsigned part[BLK_FIX];
    __shared__ int s_c;
    __shared__ unsigned s_need;
    __shared__ unsigned s_flag;
    int t = threadIdx.x;

    unsigned s = 0;
#pragma unroll
    for (int j = 0; j < 16; j++) s += g_hA[t * 16 + j];
    part[t] = s;
    __syncthreads();
    for (int d = 1; d < BLK_FIX; d <<= 1) {
        unsigned v = (t + d < BLK_FIX) ? part[t + d] : 0;
        __syncthreads();
        part[t] += v;
        __syncthreads();
    }
    long long kRem = (long long)K_TOP - (long long)g_above;
    unsigned winTotal = part[0];
    if (t == 0) { s_c = 0x7FFFFFFF; s_need = 0; }   // default: nothing from window
    __syncthreads();
    if (kRem >= 1 && kRem <= (long long)winTotal) {
        unsigned segAbove = (t < BLK_FIX - 1) ? part[t + 1] : 0;
        if ((long long)part[t] >= kRem && (long long)segAbove < kRem) {
            unsigned acc = segAbove;
            for (int j = 15; j >= 0; j--) {
                unsigned h = g_hA[t * 16 + j];
                if ((long long)(acc + h) >= kRem) {
                    s_c = t * 16 + j;
                    s_need = (unsigned)(kRem - (long long)acc);
                    break;
                }
                acc += h;
            }
        }
    } else if (kRem > (long long)winTotal) {
        if (t == 0) { s_c = -1; s_need = 0; }       // keep entire window
    }
    __syncthreads();
    const int cstar = s_c;
    const unsigned need = s_need;
    const unsigned lo = g_lo;

    unsigned n = g_nList; if (n > LIST_CAP) n = LIST_CAP;
    for (unsigned j = blockIdx.x * blockDim.x + t; j < n;
         j += gridDim.x * blockDim.x) {
        unsigned i4 = g_i4List[j];
        float4 v = x[i4];
        unsigned raw[4] = { __float_as_uint(v.x), __float_as_uint(v.y),
                            __float_as_uint(v.z), __float_as_uint(v.w) };
#pragma unroll
        for (int c = 0; c < 4; c++) {
            unsigned b = raw[c] & 0x7FFFFFFFu;
            if ((b - lo) < WIN_BINS) {
                int bucket = (int)((b - lo) >> 8);
                if (bucket > cstar) {
                    out[i4 * 4u + c] = __uint_as_float(raw[c]);
                } else if (bucket == cstar) {
                    unsigned p = atomicAdd(&g_eqCount, 1u);
                    if (p < EQ_CAP) g_eq[p] = make_uint2(i4 * 4u + c, raw[c]);
                }
            }
        }
    }

    // last block performs the exact in-bucket selection
    __threadfence();
    if (t == 0) s_flag = (atomicAdd(&g_done, 1u) == (unsigned)(gridDim.x - 1));
    __syncthreads();
    if (s_flag && need > 0) {
        __threadfence();
        unsigned cnt = *(volatile unsigned*)&g_eqCount;
        if (cnt > EQ_CAP) cnt = EQ_CAP;
        for (unsigned i = t; i < cnt; i += blockDim.x) {
            uint2 ei = g_eq[i];
            unsigned bi = ei.y & 0x7FFFFFFFu;
            unsigned rank = 0;
            for (unsigned j2 = 0; j2 < cnt; j2++) {
                uint2 ej = g_eq[j2];
                unsigned bj = ej.y & 0x7FFFFFFFu;
                rank += (bj > bi) || (bj == bi && ej.x < ei.x);
            }
            if (rank < need) out[ei.x] = __uint_as_float(ei.y);
        }
    }
}

// ---------------------------------------------------------------------------
extern "C" void kernel_launch(void* const* d_in, const int* in_sizes, int n_in,
                              void* d_out, int out_size) {
    const float* x = (const float*)d_in[0];
    float* out = (float*)d_out;

    k_zero<<<16, 256>>>();
    k_sample<<<128, 256>>>((const float4*)x);
    k_sscan<<<1, 1024>>>();
    k_main<<<GRID_MAIN, BLK_MAIN>>>((const float4*)x, (float4*)out);
    k_fixsel<<<GRID_FIX, BLK_FIX>>>((const float4*)x, out);
}